// round 11
// baseline (speedup 1.0000x reference)
#include <cuda_runtime.h>
#include <stdint.h>

#define BB 16
#define CC 19
#define HH 512
#define WW 512
#define KX 4
#define WSEG 4            // 512 / (32*KX)
#define HCH 8
#define HROWS (HH/HCH)    // 64
#define WPB 4             // warps per block (128 threads)
#define NWARPS (BB*CC*WSEG*HCH)   // 9728
#define NBLOCKS (NWARPS/WPB)      // 2432

#define B01   0x01010101u
#define TPAD  64          // front pad so (row base - 1) stays in-array

__device__ unsigned char g_tgt8[TPAD + BB*HH*WW];  // 4 MB scratch + pad
__device__ double g_acc;                     // zero-init; edge's last block resets
__device__ unsigned g_ticket;

// ---------------------------------------------------------------------------
// prep: detect int64-vs-int32 targets and convert to uint8 (L2-resident for
// the 19x channel reuse). Sampling safe for the SMALLEST possible buffer
// (int32: 4,194,304 words). int64 -> all odd words zero; int32 -> odd words
// are labels, P(all 16 samples == 0) = 19^-16 ~ 0.
// ---------------------------------------------------------------------------
__global__ void prep_kernel(const unsigned int* __restrict__ t) {
    bool is32 = false;
    #pragma unroll
    for (unsigned k = 0; k < 16; k++) {
        unsigned idx = k * 262139u + 1u;       // max 3,932,086 < 4,194,304
        is32 |= (__ldg(&t[idx | 1u]) != 0u);   // force odd
    }

    unsigned char* dst = g_tgt8 + TPAD;
    const int n4 = BB * HH * WW / 4;
    for (int i = blockIdx.x * blockDim.x + threadIdx.x; i < n4;
         i += gridDim.x * blockDim.x) {
        uchar4 o;
        if (is32) {
            uint4 v = reinterpret_cast<const uint4*>(t)[i];
            o.x = (unsigned char)v.x; o.y = (unsigned char)v.y;
            o.z = (unsigned char)v.z; o.w = (unsigned char)v.w;
        } else {
            o.x = (unsigned char)t[(4 * i + 0) * 2];
            o.y = (unsigned char)t[(4 * i + 1) * 2];
            o.z = (unsigned char)t[(4 * i + 2) * 2];
            o.w = (unsigned char)t[(4 * i + 3) * 2];
        }
        reinterpret_cast<uchar4*>(dst)[i] = o;
    }
}

// ---------------------------------------------------------------------------
// Raw row (loads only; halos via direct L1-hit neighbor loads) and derived
// per-row separable terms. Boundary handling is branch-free: float halos are
// multiplied by a per-lane {0,1} mask; target halo bytes are OR-saturated to
// 0xFF (no-class) by a per-lane constant bmask.
// ---------------------------------------------------------------------------
struct Raw  { float x0, x1, x2, x3, xl, xr; unsigned t4, th; };  // th = tl|(tr<<8)
struct RowD { float a[KX], s[KX]; unsigned u, v; };

template<bool CHK>
__device__ __forceinline__ void load_row(
    Raw& r, const float* __restrict__ plane,
    const unsigned char* __restrict__ tplane,
    int row, int w0, int offL, int offR,
    float lm, float rm, unsigned bmask)
{
    if (CHK && (unsigned)row >= (unsigned)HH) {   // warp-uniform, rare
        r.x0 = r.x1 = r.x2 = r.x3 = r.xl = r.xr = 0.f;
        r.t4 = 0xFFFFFFFFu; r.th = 0xFFFFu;       // 255 != any class
        return;
    }
    const float* xrow = plane + (size_t)row * WW;
    float4 xv = *reinterpret_cast<const float4*>(xrow + w0);
    // Neighbor-element halo loads: same L1 lines as the float4s -> hits.
    // Addresses pre-clamped in-bounds; boundary VALUE handled by mask.
    r.xl = __ldg(xrow + offL) * lm;      // lm=0 at left edge -> exact 0
    r.xr = __ldg(xrow + offR) * rm;
    r.x0 = xv.x; r.x1 = xv.y; r.x2 = xv.z; r.x3 = xv.w;

    const unsigned char* trow = tplane + (size_t)row * WW;
    unsigned t4 = *reinterpret_cast<const unsigned*>(trow + w0);
    unsigned tl = (unsigned)__ldg(trow + offL);
    unsigned tr = (unsigned)__ldg(trow + offR);
    r.t4 = t4;
    // bytes (tl, tr, 0, 0), then saturate boundary byte(s) to 0xFF
    r.th = __byte_perm(tl, tr, 0x7740u) | bmask;
}

__device__ __forceinline__ void derive(RowD& d, const Raw& r, unsigned cc4) {
    // input: diff-x / smooth-x
    d.a[0] = r.x1 - r.xl;  d.a[1] = r.x2 - r.x0;
    d.a[2] = r.x3 - r.x1;  d.a[3] = r.xr - r.x2;
    d.s[0] = fmaf(2.f, r.x0, r.xl + r.x1);
    d.s[1] = fmaf(2.f, r.x1, r.x0 + r.x2);
    d.s[2] = fmaf(2.f, r.x2, r.x1 + r.x3);
    d.s[3] = fmaf(2.f, r.x3, r.x2 + r.xr);
    // target: 2 byte-compares (center word + halo word), then permute the
    // MASKS to build the shifted windows.
    unsigned m01 = __vcmpeq4(r.t4, cc4) & B01;            // masks of t0..t3
    unsigned mh  = __vcmpeq4(r.th, cc4) & 0x00000101u;    // b0=ml, b1=mr
    unsigned ml01 = __byte_perm(m01, mh, 0x2104);  // (ml, m0, m1, m2)
    unsigned mr01 = __byte_perm(m01, mh, 0x5321);  // (m1, m2, m3, mr)
    d.u = (mr01 + B01) - ml01;            // per-byte u+1, in [0,2]; no borrow
    d.v = ml01 + mr01 + m01 * 2u;         // per-byte, in [0,4]; IMAD-friendly
}

__device__ __forceinline__ float unpack_b(unsigned w, unsigned sel) {
    // byte -> exact float via mantissa insertion; subtract (2^23 + bias 4)
    return __uint_as_float(__byte_perm(w, 0x4B000000u, sel)) - 8388612.0f;
}

__device__ __forceinline__ void emit_row(
    const RowD& P, const RowD& C0, const RowD& N, float& acc0, float& acc1)
{
    // packed target gradients, per-byte biased by +4, range [0,8]: carry-free
    unsigned gxt_b = C0.u * 2u + P.u + N.u;     // IMAD + IADD3
    unsigned gyt_b = (N.v + 0x04040404u) - P.v;
    #pragma unroll
    for (int i = 0; i < KX; i++) {
        float gx  = fmaf(2.f, C0.a[i], P.a[i] + N.a[i]);
        float gy  = N.s[i] - P.s[i];
        float ein = fabsf(gx) + fabsf(gy);
        unsigned sel = 0x7440u + (unsigned)i;
        float etg = fabsf(unpack_b(gxt_b, sel)) + fabsf(unpack_b(gyt_b, sel));
        float d = ein - etg;
        if (i & 1) acc1 = fmaf(d, d, acc1);
        else       acc0 = fmaf(d, d, acc0);
    }
}

__global__ __launch_bounds__(WPB * 32, 7)
void edge_kernel(const float* __restrict__ inp, float* __restrict__ out)
{
    const int warp = blockIdx.x * WPB + (threadIdx.x >> 5);
    const int lane = threadIdx.x & 31;

    const int wseg = warp & (WSEG - 1);
    const int hch  = (warp >> 2) & (HCH - 1);
    const int t2   = warp >> 5;               // = b*CC + c, in [0, 304)
    const unsigned c = (unsigned)(t2 % CC);
    const int b    = t2 / CC;
    const unsigned cc4 = c * 0x01010101u;

    const int wstart = wseg * (32 * KX);
    const int w0 = wstart + lane * KX;
    const bool lok = (w0 > 0);
    const bool rok = (w0 + KX < WW);
    const int offL = lok ? (w0 - 1)  : w0;    // clamped in-bounds
    const int offR = rok ? (w0 + KX) : w0;
    const float lm = lok ? 1.f : 0.f;
    const float rm = rok ? 1.f : 0.f;
    const unsigned bmask = (lok ? 0u : 0xFFu) | (rok ? 0u : 0xFF00u);
    const int h0 = hch * HROWS;
    const float* plane = inp + ((size_t)t2) * HH * WW;
    const unsigned char* tplane = g_tgt8 + TPAD + (size_t)b * HH * WW;

    float acc0 = 0.f, acc1 = 0.f;
    RowD rA, rB, rC;
    Raw q0, q1;

    // Prologue: invariant at loop top — q0 holds row y+1, q1 holds row y+2.
    // Only row h0-1 can be OOB here (hch==0).
    load_row<true >(q0, plane, tplane, h0 - 1, w0, offL, offR, lm, rm, bmask);
    load_row<false>(q1, plane, tplane, h0,     w0, offL, offR, lm, rm, bmask);
    derive(rA, q0, cc4);
    load_row<false>(q0, plane, tplane, h0 + 1, w0, offL, offR, lm, rm, bmask);
    derive(rB, q1, cc4);
    load_row<false>(q1, plane, tplane, h0 + 2, w0, offL, offR, lm, rm, bmask);

    int y = h0;
    // 6-phase body; loads rows h0+3 .. h0+62 — always in [3,510]: unchecked.
    #pragma unroll 1
    for (int it = 0; it < 10; ++it) {
        derive(rC, q0, cc4);
        load_row<false>(q0, plane, tplane, y + 3, w0, offL, offR, lm, rm, bmask);
        emit_row(rA, rB, rC, acc0, acc1); ++y;
        derive(rA, q1, cc4);
        load_row<false>(q1, plane, tplane, y + 3, w0, offL, offR, lm, rm, bmask);
        emit_row(rB, rC, rA, acc0, acc1); ++y;
        derive(rB, q0, cc4);
        load_row<false>(q0, plane, tplane, y + 3, w0, offL, offR, lm, rm, bmask);
        emit_row(rC, rA, rB, acc0, acc1); ++y;
        derive(rC, q1, cc4);
        load_row<false>(q1, plane, tplane, y + 3, w0, offL, offR, lm, rm, bmask);
        emit_row(rA, rB, rC, acc0, acc1); ++y;
        derive(rA, q0, cc4);
        load_row<false>(q0, plane, tplane, y + 3, w0, offL, offR, lm, rm, bmask);
        emit_row(rB, rC, rA, acc0, acc1); ++y;
        derive(rB, q1, cc4);
        load_row<false>(q1, plane, tplane, y + 3, w0, offL, offR, lm, rm, bmask);
        emit_row(rC, rA, rB, acc0, acc1); ++y;
    }
    // Epilogue: rows h0+60..63. Row h0+63 always valid; h0+64 checked (hch==7).
    derive(rC, q0, cc4);
    load_row<false>(q0, plane, tplane, y + 3, w0, offL, offR, lm, rm, bmask);
    emit_row(rA, rB, rC, acc0, acc1); ++y;
    derive(rA, q1, cc4);
    load_row<true >(q1, plane, tplane, y + 3, w0, offL, offR, lm, rm, bmask);
    emit_row(rB, rC, rA, acc0, acc1); ++y;
    derive(rB, q0, cc4); emit_row(rC, rA, rB, acc0, acc1); ++y;
    derive(rC, q1, cc4); emit_row(rA, rB, rC, acc0, acc1);

    // reduce: warp -> block -> global double; last block finalizes + resets.
    float acc = acc0 + acc1;
    #pragma unroll
    for (int o = 16; o; o >>= 1) acc += __shfl_xor_sync(0xffffffffu, acc, o);
    __shared__ float ws[WPB];
    if (lane == 0) ws[threadIdx.x >> 5] = acc;
    __syncthreads();
    if (threadIdx.x == 0) {
        double s = 0.0;
        #pragma unroll
        for (int i = 0; i < WPB; i++) s += (double)ws[i];
        atomicAdd(&g_acc, s);
        __threadfence();
        unsigned t = atomicAdd(&g_ticket, 1u);
        if (t == (unsigned)(NBLOCKS - 1)) {
            double v = atomicAdd(&g_acc, 0.0);   // ordered read
            out[0] = (float)(v * (1.0 / ((double)BB * HH * WW)));
            g_acc = 0.0;                          // reset for next replay
            g_ticket = 0u;
        }
    }
}

// ---------------------------------------------------------------------------
extern "C" void kernel_launch(void* const* d_in, const int* in_sizes, int n_in,
                              void* d_out, int out_size)
{
    const float* inp;
    const unsigned int* tgt;
    if (in_sizes[0] == BB * CC * HH * WW) {
        inp = (const float*)d_in[0];
        tgt = (const unsigned int*)d_in[1];
    } else {
        inp = (const float*)d_in[1];
        tgt = (const unsigned int*)d_in[0];
    }
    float* out = (float*)d_out;

    prep_kernel<<<1184, 256>>>(tgt);
    edge_kernel<<<NBLOCKS, WPB * 32>>>(inp, out);
}